// round 14
// baseline (speedup 1.0000x reference)
#include <cuda_runtime.h>
#include <cstdint>

static constexpr int KC = 5;
static constexpr int DC = 10;
static constexpr int NBINS = 8192;
static constexpr float EPS_MARGIN = 2e-5f;

static constexpr int TILE_F4 = 512;                 // float4s per tile (8 KB)
static constexpr int TILE_BYTES = TILE_F4 * 16;

__device__ unsigned char g_lut[NBINS];

__device__ __constant__ int PAIR_A[10] = {0,0,0,0,1,1,1,2,2,3};
__device__ __constant__ int PAIR_B[10] = {1,2,3,4,2,3,4,3,4,4};
__device__ __constant__ int PAIR_OFF[4] = {0,4,7,9};

// ---------------- Kernel A: streaming two-pass builder ----------------
__global__ __launch_bounds__(256) void vq_build_lut(const float* __restrict__ emb)
{
    int bin = blockIdx.x * blockDim.x + threadIdx.x;
    if (bin >= NBINS) return;

    float c[KC - 1][DC], d[KC - 1];
    {
        float e0[DC], s0 = 0.0f;
        #pragma unroll
        for (int i = 0; i < DC; i++) { e0[i] = emb[i]; s0 = fmaf(e0[i], e0[i], s0); }
        #pragma unroll
        for (int k = 1; k < KC; k++) {
            float sk = 0.0f;
            #pragma unroll
            for (int i = 0; i < DC; i++) {
                float e = emb[k * DC + i];
                sk = fmaf(e, e, sk);
                c[k - 1][i] = -2.0f * (e - e0[i]);
            }
            d[k - 1] = sk - s0;
        }
    }

    // Pass 1: streaming — candidate mask + definite-winner certification.
    unsigned mask = 0;
    int w0 = -1;
    bool def_ok = true;
    #pragma unroll
    for (int t = 0; t < 7; t++) {
        float v = ((float)bin + 0.25f * (float)(t - 1)) * (1.0f / (float)NBINS);
        float sc0 = 0.0f, sc[KC - 1];
        #pragma unroll
        for (int k = 0; k < KC - 1; k++) {
            float h = c[k][DC - 1];
            #pragma unroll
            for (int j = DC - 2; j >= 0; j--) h = fmaf(h, v, c[k][j]);
            sc[k] = fmaf(h, v, d[k]);
        }
        int w = 0; float best = sc0;
        #pragma unroll
        for (int k = 0; k < KC - 1; k++)
            if (sc[k] < best) { best = sc[k]; w = k + 1; }
        int r = -1; float sec = 3.4e38f;
        if (w != 0 && sc0 < sec) { sec = sc0; r = 0; }
        #pragma unroll
        for (int k = 0; k < KC - 1; k++)
            if (k + 1 != w && sc[k] < sec) { sec = sc[k]; r = k + 1; }
        if (t == 0) w0 = w;
        mask |= 1u << w;
        if (sec - best <= EPS_MARGIN) mask |= 1u << r;
        def_ok = def_ok && (w == w0) && (sec - best > EPS_MARGIN);
    }

    unsigned char byte = 255;
    int pc = __popc(mask);
    if (bin == 0 || bin == NBINS - 1) {
        byte = 255;
    } else if (pc == 1 && def_ok) {
        byte = (unsigned char)(__ffs(mask) - 1);
    } else if (pc == 2) {
        // Pass 2 (rare): certify the pair — all outside codes trail by margin.
        int kA = __ffs(mask) - 1;
        int kB = 31 - __clz(mask);
        bool ok = true;
        for (int t = 0; t < 7; t++) {
            float v = ((float)bin + 0.25f * (float)(t - 1)) * (1.0f / (float)NBINS);
            float sc[KC];
            sc[0] = 0.0f;
            #pragma unroll
            for (int k = 0; k < KC - 1; k++) {
                float h = c[k][DC - 1];
                #pragma unroll
                for (int j = DC - 2; j >= 0; j--) h = fmaf(h, v, c[k][j]);
                sc[k + 1] = fmaf(h, v, d[k]);
            }
            float minIn = fminf(sc[kA], sc[kB]);
            float minOut = 3.4e38f;
            #pragma unroll
            for (int k = 0; k < KC; k++)
                if (k != kA && k != kB) minOut = fminf(minOut, sc[k]);
            ok = ok && (minOut - minIn > EPS_MARGIN);
        }
        if (ok) byte = (unsigned char)(128 + PAIR_OFF[kA] + kB - kA - 1);
    }
    g_lut[bin] = byte;
}

// ---------------- Rare full fallback (out of line) ----------------
__device__ __noinline__ float vq_full_fallback(float v, const float* scoef) {
    float g[KC - 1];
    #pragma unroll
    for (int k = 0; k < KC - 1; k++) {
        float h = scoef[k * DC + DC - 1];
        #pragma unroll
        for (int j = DC - 2; j >= 0; j--) h = fmaf(h, v, scoef[k * DC + j]);
        g[k] = fmaf(h, v, scoef[(KC - 1) * DC + k]);
    }
    float best = 0.0f, idx = 0.0f;
    idx = (g[0] < best) ? 1.0f : idx;  best = fminf(g[0], best);
    idx = (g[1] < best) ? 2.0f : idx;  best = fminf(g[1], best);
    idx = (g[2] < best) ? 3.0f : idx;  best = fminf(g[2], best);
    idx = (g[3] < best) ? 4.0f : idx;  best = fminf(g[3], best);
    return idx;
}

// ---------------- mbarrier / bulk-async helpers ----------------
__device__ __forceinline__ unsigned smem_u32(const void* p) {
    return (unsigned)__cvta_generic_to_shared(p);
}
__device__ __forceinline__ void mbar_init(unsigned a, unsigned cnt) {
    asm volatile("mbarrier.init.shared.b64 [%0], %1;" :: "r"(a), "r"(cnt) : "memory");
}
__device__ __forceinline__ void mbar_expect_tx(unsigned a, unsigned bytes) {
    asm volatile("mbarrier.arrive.expect_tx.shared.b64 _, [%0], %1;"
                 :: "r"(a), "r"(bytes) : "memory");
}
__device__ __forceinline__ void bulk_g2s(unsigned sdst, const void* gsrc,
                                         unsigned bytes, unsigned mbar) {
    asm volatile("cp.async.bulk.shared::cta.global.mbarrier::complete_tx::bytes "
                 "[%0], [%1], %2, [%3];"
                 :: "r"(sdst), "l"(gsrc), "r"(bytes), "r"(mbar) : "memory");
}
__device__ __forceinline__ void mbar_wait(unsigned a, unsigned phase) {
    unsigned done = 0;
    while (!done) {
        asm volatile(
            "{\n\t.reg .pred p;\n\t"
            "mbarrier.try_wait.parity.acquire.cta.shared::cta.b64 p, [%1], %2, 0x989680;\n\t"
            "selp.b32 %0, 1, 0, p;\n\t}"
            : "=r"(done) : "r"(a), "r"(phase) : "memory");
    }
}

// ---------------- Kernel B: bulk-async staged LUT map ----------------
__global__ __launch_bounds__(128, 7) void vq_map(
    const float* __restrict__ x, const float* __restrict__ emb,
    float* __restrict__ out, int n)
{
    __shared__ alignas(16) float4 sbuf[2][TILE_F4];       // 16 KB
    __shared__ unsigned char slut[NBINS];                  // 8 KB
    __shared__ float scoef[(KC - 1) * DC + (KC - 1)];
    __shared__ float pcoef[10 * 11];
    __shared__ float pAB[20];
    __shared__ alignas(8) unsigned long long mbar_s[2];

    const int tid = threadIdx.x;

    if (tid == 0) {
        mbar_init(smem_u32(&mbar_s[0]), 1);
        mbar_init(smem_u32(&mbar_s[1]), 1);
    }
    {
        const uint4* src = (const uint4*)g_lut;
        uint4* dst = (uint4*)slut;
        #pragma unroll
        for (int i = tid; i < NBINS / 16; i += 128) dst[i] = src[i];
    }
    for (int t = tid; t < 44; t += 128) {
        if (t < (KC - 1) * DC) {
            int k = t / DC + 1, j = t % DC;
            scoef[t] = -2.0f * (emb[k * DC + j] - emb[j]);
        } else {
            int k = t - (KC - 1) * DC + 1;
            float sk = 0.0f, s0 = 0.0f;
            #pragma unroll
            for (int i = 0; i < DC; i++) {
                float ek = emb[k * DC + i], e0 = emb[i];
                sk = fmaf(ek, ek, sk);
                s0 = fmaf(e0, e0, s0);
            }
            scoef[t] = sk - s0;
        }
    }
    for (int u = tid; u < 110; u += 128) {
        int p = u / 11, j = u % 11;
        int a = PAIR_A[p], b = PAIR_B[p];
        if (j < DC) {
            pcoef[u] = -2.0f * (emb[a * DC + j] - emb[b * DC + j]);
        } else {
            float sa = 0.0f, sb = 0.0f;
            #pragma unroll
            for (int i = 0; i < DC; i++) {
                float ea = emb[a * DC + i], eb = emb[b * DC + i];
                sa = fmaf(ea, ea, sa);
                sb = fmaf(eb, eb, sb);
            }
            pcoef[u] = sa - sb;
        }
    }
    for (int p = tid; p < 10; p += 128) {
        pAB[2 * p]     = (float)PAIR_A[p];
        pAB[2 * p + 1] = (float)PAIR_B[p];
    }
    __syncthreads();   // mbarrier init + tables visible to all threads

    auto resolve = [&](unsigned code, float v) -> float {
        if (code == 255u) return vq_full_fallback(v, scoef);
        int p = (int)code - 128;
        const float* pb = &pcoef[p * 11];
        float h = pb[DC - 1];
        #pragma unroll
        for (int j = DC - 2; j >= 0; j--) h = fmaf(h, v, pb[j]);
        float delta = fmaf(h, v, pb[DC]);               // g_kA - g_kB
        return (delta <= 0.0f) ? pAB[2 * p] : pAB[2 * p + 1];
    };
    auto lookup = [&](float v) -> unsigned {
        int b = (int)(v * (float)NBINS);
        b = max(b, 0);
        b = min(b, NBINS - 1);
        return (unsigned)slut[b];
    };
    auto quant4 = [&](float4 a) -> float4 {
        unsigned c0 = lookup(a.x), c1 = lookup(a.y),
                 c2 = lookup(a.z), c3 = lookup(a.w);
        float r0 = (float)c0, r1 = (float)c1, r2 = (float)c2, r3 = (float)c3;
        if ((c0 | c1 | c2 | c3) & 0x80u) {
            if (c0 & 0x80u) r0 = resolve(c0, a.x);
            if (c1 & 0x80u) r1 = resolve(c1, a.y);
            if (c2 & 0x80u) r2 = resolve(c2, a.z);
            if (c3 & 0x80u) r3 = resolve(c3, a.w);
        }
        return make_float4(r0, r1, r2, r3);
    };

    const int n4 = n >> 2;
    const int ntiles = n4 / TILE_F4;
    const float4* __restrict__ x4 = (const float4*)x;
    float4* __restrict__ o4 = (float4*)out;
    const int g = gridDim.x;

    const unsigned mb[2] = { smem_u32(&mbar_s[0]), smem_u32(&mbar_s[1]) };
    const unsigned sb[2] = { smem_u32(&sbuf[0][0]), smem_u32(&sbuf[1][0]) };

    // Prologue: stage first two tiles.
    int t0 = blockIdx.x;
    if (tid == 0 && t0 < ntiles) {
        mbar_expect_tx(mb[0], TILE_BYTES);
        bulk_g2s(sb[0], x4 + (size_t)t0 * TILE_F4, TILE_BYTES, mb[0]);
    }
    if (tid == 0 && t0 + g < ntiles) {
        mbar_expect_tx(mb[1], TILE_BYTES);
        bulk_g2s(sb[1], x4 + (size_t)(t0 + g) * TILE_F4, TILE_BYTES, mb[1]);
    }

    int ph[2] = {0, 0};
    int k = 0;
    for (int tile = t0; tile < ntiles; tile += g, k++) {
        int b = k & 1;
        mbar_wait(mb[b], ph[b]);
        ph[b] ^= 1;

        float4* obase = o4 + (size_t)tile * TILE_F4;
        #pragma unroll
        for (int j = 0; j < TILE_F4 / 128; j++) {
            float4 a = sbuf[b][tid + j * 128];
            obase[tid + j * 128] = quant4(a);
        }

        __syncthreads();                      // everyone done reading sbuf[b]
        int nt = tile + 2 * g;
        if (tid == 0 && nt < ntiles) {
            mbar_expect_tx(mb[b], TILE_BYTES);
            bulk_g2s(sb[b], x4 + (size_t)nt * TILE_F4, TILE_BYTES, mb[b]);
        }
    }

    // Leftover float4s beyond the tiled region (direct LDG path).
    const int gtid = blockIdx.x * blockDim.x + tid;
    const int gstride = g * blockDim.x;
    for (int i = ntiles * TILE_F4 + gtid; i < n4; i += gstride)
        o4[i] = quant4(x4[i]);

    // Scalar tail (n % 4): exact fallback.
    for (int t = (n4 << 2) + gtid; t < n; t += gstride)
        out[t] = vq_full_fallback(x[t], scoef);
}

extern "C" void kernel_launch(void* const* d_in, const int* in_sizes, int n_in,
                              void* d_out, int out_size)
{
    const float* x   = (const float*)d_in[0];
    const float* emb = (const float*)d_in[1];
    if (n_in >= 2 && in_sizes[0] == KC * DC && in_sizes[1] != KC * DC) {
        x   = (const float*)d_in[1];
        emb = (const float*)d_in[0];
    }
    float* out = (float*)d_out;
    int n = out_size;

    vq_build_lut<<<NBINS / 256, 256>>>(emb);
    vq_map<<<1036, 128>>>(x, emb, out, n);   // 7 CTAs/SM, one wave
}

// round 16
// speedup vs baseline: 1.0744x; 1.0744x over previous
#include <cuda_runtime.h>
#include <cstdint>

static constexpr int KC = 5;
static constexpr int DC = 10;
static constexpr int NBINS = 8192;
static constexpr float EPS_MARGIN = 2e-5f;

__device__ unsigned char g_lut[NBINS];

__device__ __constant__ int PAIR_A[10] = {0,0,0,0,1,1,1,2,2,3};
__device__ __constant__ int PAIR_B[10] = {1,2,3,4,2,3,4,3,4,4};
__device__ __constant__ int PAIR_OFF[4] = {0,4,7,9};

// ---------------- Kernel A: streaming two-pass builder ----------------
__global__ __launch_bounds__(128) void vq_build_lut(const float* __restrict__ emb)
{
    int bin = blockIdx.x * blockDim.x + threadIdx.x;
    if (bin < NBINS) {
        float c[KC - 1][DC], d[KC - 1];
        {
            float e0[DC], s0 = 0.0f;
            #pragma unroll
            for (int i = 0; i < DC; i++) { e0[i] = emb[i]; s0 = fmaf(e0[i], e0[i], s0); }
            #pragma unroll
            for (int k = 1; k < KC; k++) {
                float sk = 0.0f;
                #pragma unroll
                for (int i = 0; i < DC; i++) {
                    float e = emb[k * DC + i];
                    sk = fmaf(e, e, sk);
                    c[k - 1][i] = -2.0f * (e - e0[i]);
                }
                d[k - 1] = sk - s0;
            }
        }

        // Pass 1: candidate mask + definite-winner certification (7 dilated samples).
        unsigned mask = 0;
        int w0 = -1;
        bool def_ok = true;
        #pragma unroll
        for (int t = 0; t < 7; t++) {
            float v = ((float)bin + 0.25f * (float)(t - 1)) * (1.0f / (float)NBINS);
            float sc0 = 0.0f, sc[KC - 1];
            #pragma unroll
            for (int k = 0; k < KC - 1; k++) {
                float h = c[k][DC - 1];
                #pragma unroll
                for (int j = DC - 2; j >= 0; j--) h = fmaf(h, v, c[k][j]);
                sc[k] = fmaf(h, v, d[k]);
            }
            int w = 0; float best = sc0;
            #pragma unroll
            for (int k = 0; k < KC - 1; k++)
                if (sc[k] < best) { best = sc[k]; w = k + 1; }
            int r = -1; float sec = 3.4e38f;
            if (w != 0 && sc0 < sec) { sec = sc0; r = 0; }
            #pragma unroll
            for (int k = 0; k < KC - 1; k++)
                if (k + 1 != w && sc[k] < sec) { sec = sc[k]; r = k + 1; }
            if (t == 0) w0 = w;
            mask |= 1u << w;
            if (sec - best <= EPS_MARGIN) mask |= 1u << r;
            def_ok = def_ok && (w == w0) && (sec - best > EPS_MARGIN);
        }

        unsigned char byte = 255;
        int pc = __popc(mask);
        if (bin == 0 || bin == NBINS - 1) {
            byte = 255;
        } else if (pc == 1 && def_ok) {
            byte = (unsigned char)(__ffs(mask) - 1);
        } else if (pc == 2) {
            // Pass 2 (rare): certify the pair — outside codes trail by margin.
            int kA = __ffs(mask) - 1;
            int kB = 31 - __clz(mask);
            bool ok = true;
            #pragma unroll
            for (int t = 0; t < 7; t++) {
                float v = ((float)bin + 0.25f * (float)(t - 1)) * (1.0f / (float)NBINS);
                float sc[KC];
                sc[0] = 0.0f;
                #pragma unroll
                for (int k = 0; k < KC - 1; k++) {
                    float h = c[k][DC - 1];
                    #pragma unroll
                    for (int j = DC - 2; j >= 0; j--) h = fmaf(h, v, c[k][j]);
                    sc[k + 1] = fmaf(h, v, d[k]);
                }
                float minIn = fminf(sc[kA], sc[kB]);
                float minOut = 3.4e38f;
                #pragma unroll
                for (int k = 0; k < KC; k++)
                    if (k != kA && k != kB) minOut = fminf(minOut, sc[k]);
                ok = ok && (minOut - minIn > EPS_MARGIN);
            }
            if (ok) byte = (unsigned char)(128 + PAIR_OFF[kA] + kB - kA - 1);
        }
        g_lut[bin] = byte;
    }

    // Let a PDL-dependent grid start as early as possible (no-op without PDL).
    cudaTriggerProgrammaticLaunchCompletion();
}

// ---------------- Rare full fallback (out of line) ----------------
__device__ __noinline__ float vq_full_fallback(float v, const float* scoef) {
    float g[KC - 1];
    #pragma unroll
    for (int k = 0; k < KC - 1; k++) {
        float h = scoef[k * DC + DC - 1];
        #pragma unroll
        for (int j = DC - 2; j >= 0; j--) h = fmaf(h, v, scoef[k * DC + j]);
        g[k] = fmaf(h, v, scoef[(KC - 1) * DC + k]);
    }
    float best = 0.0f, idx = 0.0f;
    idx = (g[0] < best) ? 1.0f : idx;  best = fminf(g[0], best);
    idx = (g[1] < best) ? 2.0f : idx;  best = fminf(g[1], best);
    idx = (g[2] < best) ? 3.0f : idx;  best = fminf(g[2], best);
    idx = (g[3] < best) ? 4.0f : idx;  best = fminf(g[3], best);
    return idx;
}

// ---------------- Kernel B: LUT map, depth-2 pipeline + streaming stores ----------------
__global__ __launch_bounds__(128, 7) void vq_map(
    const float* __restrict__ x, const float* __restrict__ emb,
    float* __restrict__ out, int n)
{
    __shared__ unsigned char slut[NBINS];                // 8 KB
    __shared__ float scoef[(KC - 1) * DC + (KC - 1)];    // 44
    __shared__ float pcoef[10 * 11];                     // 110
    __shared__ float pAB[20];

    // Prologue independent of g_lut: coefficient tables from emb.
    for (int t = threadIdx.x; t < 44; t += 128) {
        if (t < (KC - 1) * DC) {
            int k = t / DC + 1, j = t % DC;
            scoef[t] = -2.0f * (emb[k * DC + j] - emb[j]);
        } else {
            int k = t - (KC - 1) * DC + 1;
            float sk = 0.0f, s0 = 0.0f;
            #pragma unroll
            for (int i = 0; i < DC; i++) {
                float ek = emb[k * DC + i], e0 = emb[i];
                sk = fmaf(ek, ek, sk);
                s0 = fmaf(e0, e0, s0);
            }
            scoef[t] = sk - s0;
        }
    }
    for (int u = threadIdx.x; u < 110; u += 128) {
        int p = u / 11, j = u % 11;
        int a = PAIR_A[p], b = PAIR_B[p];
        if (j < DC) {
            pcoef[u] = -2.0f * (emb[a * DC + j] - emb[b * DC + j]);
        } else {
            float sa = 0.0f, sb = 0.0f;
            #pragma unroll
            for (int i = 0; i < DC; i++) {
                float ea = emb[a * DC + i], eb = emb[b * DC + i];
                sa = fmaf(ea, ea, sa);
                sb = fmaf(eb, eb, sb);
            }
            pcoef[u] = sa - sb;
        }
    }
    for (int p = threadIdx.x; p < 10; p += 128) {
        pAB[2 * p]     = (float)PAIR_A[p];
        pAB[2 * p + 1] = (float)PAIR_B[p];
    }

    // Gate on the builder's g_lut (immediate no-op when PDL is inactive).
    cudaGridDependencySynchronize();
    {
        const uint4* src = (const uint4*)g_lut;
        uint4* dst = (uint4*)slut;
        #pragma unroll
        for (int i = threadIdx.x; i < NBINS / 16; i += 128) dst[i] = src[i];
    }
    __syncthreads();

    auto resolve = [&](unsigned code, float v) -> float {
        if (code == 255u) return vq_full_fallback(v, scoef);
        int p = (int)code - 128;
        const float* pb = &pcoef[p * 11];
        float h = pb[DC - 1];
        #pragma unroll
        for (int j = DC - 2; j >= 0; j--) h = fmaf(h, v, pb[j]);
        float delta = fmaf(h, v, pb[DC]);                 // g_kA - g_kB
        return (delta <= 0.0f) ? pAB[2 * p] : pAB[2 * p + 1];  // tie -> lower idx
    };
    auto lookup = [&](float v) -> unsigned {
        int b = (int)(v * (float)NBINS);
        b = max(b, 0);
        b = min(b, NBINS - 1);
        return (unsigned)slut[b];
    };

    const int n4 = n >> 2;
    const float4* __restrict__ x4 = (const float4*)x;
    float4* __restrict__ o4 = (float4*)out;
    const int stride = gridDim.x * blockDim.x;
    int i = blockIdx.x * blockDim.x + threadIdx.x;

    // Depth-2 circular register pipeline: two LDG.128 in flight per warp.
    float4 b0, b1;
    if (i < n4)           b0 = x4[i];
    if (i + stride < n4)  b1 = x4[i + stride];

    for (; i < n4; i += stride) {
        int ip2 = i + 2 * stride;
        float4 nxt;
        if (ip2 < n4) nxt = x4[ip2];       // issued before the dependent chain

        unsigned c0 = lookup(b0.x);
        unsigned c1 = lookup(b0.y);
        unsigned c2 = lookup(b0.z);
        unsigned c3 = lookup(b0.w);

        float r0 = (float)c0, r1 = (float)c1, r2 = (float)c2, r3 = (float)c3;
        if ((c0 | c1 | c2 | c3) & 0x80u) {
            if (c0 & 0x80u) r0 = resolve(c0, b0.x);
            if (c1 & 0x80u) r1 = resolve(c1, b0.y);
            if (c2 & 0x80u) r2 = resolve(c2, b0.z);
            if (c3 & 0x80u) r3 = resolve(c3, b0.w);
        }
        __stcs(&o4[i], make_float4(r0, r1, r2, r3));   // streaming store: keep x in L2
        b0 = b1;
        b1 = nxt;
    }

    for (int t = (n4 << 2) + blockIdx.x * blockDim.x + threadIdx.x; t < n; t += stride)
        out[t] = vq_full_fallback(x[t], scoef);
}

extern "C" void kernel_launch(void* const* d_in, const int* in_sizes, int n_in,
                              void* d_out, int out_size)
{
    const float* x   = (const float*)d_in[0];
    const float* emb = (const float*)d_in[1];
    if (n_in >= 2 && in_sizes[0] == KC * DC && in_sizes[1] != KC * DC) {
        x   = (const float*)d_in[1];
        emb = (const float*)d_in[0];
    }
    float* out = (float*)d_out;
    int n = out_size;

    vq_build_lut<<<NBINS / 128, 128>>>(emb);

    // Try PDL launch (overlaps builder tail with the map prologue). If the
    // attribute path fails for any reason, fall back to a plain launch —
    // stream order still guarantees g_lut is ready.
    cudaLaunchConfig_t cfg = {};
    cfg.gridDim  = dim3(1036, 1, 1);
    cfg.blockDim = dim3(128, 1, 1);
    cfg.dynamicSmemBytes = 0;
    cfg.stream = 0;
    cudaLaunchAttribute attr[1];
    attr[0].id = cudaLaunchAttributeProgrammaticStreamSerialization;
    attr[0].val.programmaticStreamSerializationAllowed = 1;
    cfg.attrs = attr;
    cfg.numAttrs = 1;
    cudaError_t err = cudaLaunchKernelEx(&cfg, vq_map, x, emb, out, n);
    if (err != cudaSuccess) {
        (void)cudaGetLastError();            // clear sticky error
        vq_map<<<1036, 128>>>(x, emb, out, n);
    }
}

// round 17
// speedup vs baseline: 1.1857x; 1.1037x over previous
#include <cuda_runtime.h>
#include <cstdint>

static constexpr int KC = 5;
static constexpr int DC = 10;
static constexpr int NBINS = 8192;          // 2^13
static constexpr float EPS_MARGIN = 2e-5f;

__device__ unsigned char g_lut[NBINS];

__device__ __constant__ int PAIR_A[10] = {0,0,0,0,1,1,1,2,2,3};
__device__ __constant__ int PAIR_B[10] = {1,2,3,4,2,3,4,3,4,4};
__device__ __constant__ int PAIR_OFF[4] = {0,4,7,9};

// ---------------- Kernel A: streaming two-pass builder ----------------
__global__ __launch_bounds__(128) void vq_build_lut(const float* __restrict__ emb)
{
    int bin = blockIdx.x * blockDim.x + threadIdx.x;
    if (bin < NBINS) {
        float c[KC - 1][DC], d[KC - 1];
        {
            float e0[DC], s0 = 0.0f;
            #pragma unroll
            for (int i = 0; i < DC; i++) { e0[i] = emb[i]; s0 = fmaf(e0[i], e0[i], s0); }
            #pragma unroll
            for (int k = 1; k < KC; k++) {
                float sk = 0.0f;
                #pragma unroll
                for (int i = 0; i < DC; i++) {
                    float e = emb[k * DC + i];
                    sk = fmaf(e, e, sk);
                    c[k - 1][i] = -2.0f * (e - e0[i]);
                }
                d[k - 1] = sk - s0;
            }
        }

        unsigned mask = 0;
        int w0 = -1;
        bool def_ok = true;
        #pragma unroll
        for (int t = 0; t < 7; t++) {
            float v = ((float)bin + 0.25f * (float)(t - 1)) * (1.0f / (float)NBINS);
            float sc0 = 0.0f, sc[KC - 1];
            #pragma unroll
            for (int k = 0; k < KC - 1; k++) {
                float h = c[k][DC - 1];
                #pragma unroll
                for (int j = DC - 2; j >= 0; j--) h = fmaf(h, v, c[k][j]);
                sc[k] = fmaf(h, v, d[k]);
            }
            int w = 0; float best = sc0;
            #pragma unroll
            for (int k = 0; k < KC - 1; k++)
                if (sc[k] < best) { best = sc[k]; w = k + 1; }
            int r = -1; float sec = 3.4e38f;
            if (w != 0 && sc0 < sec) { sec = sc0; r = 0; }
            #pragma unroll
            for (int k = 0; k < KC - 1; k++)
                if (k + 1 != w && sc[k] < sec) { sec = sc[k]; r = k + 1; }
            if (t == 0) w0 = w;
            mask |= 1u << w;
            if (sec - best <= EPS_MARGIN) mask |= 1u << r;
            def_ok = def_ok && (w == w0) && (sec - best > EPS_MARGIN);
        }

        unsigned char byte = 255;
        int pc = __popc(mask);
        if (bin == 0 || bin == NBINS - 1) {
            byte = 255;                      // edge bins: exact path
        } else if (pc == 1 && def_ok) {
            byte = (unsigned char)(__ffs(mask) - 1);
        } else if (pc == 2) {
            int kA = __ffs(mask) - 1;
            int kB = 31 - __clz(mask);
            bool ok = true;
            #pragma unroll
            for (int t = 0; t < 7; t++) {
                float v = ((float)bin + 0.25f * (float)(t - 1)) * (1.0f / (float)NBINS);
                float sc[KC];
                sc[0] = 0.0f;
                #pragma unroll
                for (int k = 0; k < KC - 1; k++) {
                    float h = c[k][DC - 1];
                    #pragma unroll
                    for (int j = DC - 2; j >= 0; j--) h = fmaf(h, v, c[k][j]);
                    sc[k + 1] = fmaf(h, v, d[k]);
                }
                float minIn = fminf(sc[kA], sc[kB]);
                float minOut = 3.4e38f;
                #pragma unroll
                for (int k = 0; k < KC; k++)
                    if (k != kA && k != kB) minOut = fminf(minOut, sc[k]);
                ok = ok && (minOut - minIn > EPS_MARGIN);
            }
            if (ok) byte = (unsigned char)(128 + PAIR_OFF[kA] + kB - kA - 1);
        }
        g_lut[bin] = byte;
    }
    cudaTriggerProgrammaticLaunchCompletion();
}

// ---------------- Rare full fallback (out of line) ----------------
__device__ __noinline__ float vq_full_fallback(float v, const float* scoef) {
    float g[KC - 1];
    #pragma unroll
    for (int k = 0; k < KC - 1; k++) {
        float h = scoef[k * DC + DC - 1];
        #pragma unroll
        for (int j = DC - 2; j >= 0; j--) h = fmaf(h, v, scoef[k * DC + j]);
        g[k] = fmaf(h, v, scoef[(KC - 1) * DC + k]);
    }
    float best = 0.0f, idx = 0.0f;
    idx = (g[0] < best) ? 1.0f : idx;  best = fminf(g[0], best);
    idx = (g[1] < best) ? 2.0f : idx;  best = fminf(g[1], best);
    idx = (g[2] < best) ? 3.0f : idx;  best = fminf(g[2], best);
    idx = (g[3] < best) ? 4.0f : idx;  best = fminf(g[3], best);
    return idx;
}

// ---------------- Kernel B: 256thr/4CTA map, depth-2 pipeline, bit-trick bin ----------------
__global__ __launch_bounds__(256, 4) void vq_map(
    const float* __restrict__ x, const float* __restrict__ emb,
    float* __restrict__ out, int n)
{
    __shared__ unsigned char slut[NBINS];                // 8 KB
    __shared__ float scoef[(KC - 1) * DC + (KC - 1)];
    __shared__ float pcoef[10 * 11];
    __shared__ float pAB[20];

    // Prologue independent of g_lut.
    {
        int t = threadIdx.x;
        if (t < (KC - 1) * DC) {
            int k = t / DC + 1, j = t % DC;
            scoef[t] = -2.0f * (emb[k * DC + j] - emb[j]);
        } else if (t < (KC - 1) * DC + (KC - 1)) {
            int k = t - (KC - 1) * DC + 1;
            float sk = 0.0f, s0 = 0.0f;
            #pragma unroll
            for (int i = 0; i < DC; i++) {
                float ek = emb[k * DC + i], e0 = emb[i];
                sk = fmaf(ek, ek, sk);
                s0 = fmaf(e0, e0, s0);
            }
            scoef[t] = sk - s0;
        }
        int u = t - 64;
        if (u >= 0 && u < 110) {
            int p = u / 11, j = u % 11;
            int a = PAIR_A[p], b = PAIR_B[p];
            if (j < DC) {
                pcoef[u] = -2.0f * (emb[a * DC + j] - emb[b * DC + j]);
            } else {
                float sa = 0.0f, sb = 0.0f;
                #pragma unroll
                for (int i = 0; i < DC; i++) {
                    float ea = emb[a * DC + i], eb = emb[b * DC + i];
                    sa = fmaf(ea, ea, sa);
                    sb = fmaf(eb, eb, sb);
                }
                pcoef[u] = sa - sb;
            }
        }
        if (t >= 192 && t < 202) {
            int p = t - 192;
            pAB[2 * p]     = (float)PAIR_A[p];
            pAB[2 * p + 1] = (float)PAIR_B[p];
        }
    }

    // Gate on the builder's g_lut (no-op when PDL inactive), then stage it.
    cudaGridDependencySynchronize();
    {
        const uint4* src = (const uint4*)g_lut;
        uint4* dst = (uint4*)slut;
        #pragma unroll
        for (int i = threadIdx.x; i < NBINS / 16; i += 256) dst[i] = src[i];
    }
    __syncthreads();

    auto resolve = [&](unsigned code, float v) -> float {
        if (code == 255u) return vq_full_fallback(v, scoef);
        int p = (int)code - 128;
        const float* pb = &pcoef[p * 11];
        float h = pb[DC - 1];
        #pragma unroll
        for (int j = DC - 2; j >= 0; j--) h = fmaf(h, v, pb[j]);
        float delta = fmaf(h, v, pb[DC]);                 // g_kA - g_kB
        return (delta <= 0.0f) ? pAB[2 * p] : pAB[2 * p + 1];  // tie -> lower idx
    };

    // Bit-trick bin: for v in [0,1), bits(1+v) mantissa = v*2^23; top 13 bits = bin.
    // u32 clamp covers v<0 / v>=1 (map to bin 0 / 8191 = sentinel-safe edges).
    // Boundary rounding is +/-1 bin at most, covered by the builder's dilation.
    auto lookup = [&](float v) -> unsigned {
        unsigned u = __float_as_uint(v + 1.0f);
        u = ::min(::max(u, 0x3F800000u), 0x3FFFFFFFu);
        return (unsigned)slut[(u >> 10) & (NBINS - 1)];
    };

    const int n4 = n >> 2;
    const float4* __restrict__ x4 = (const float4*)x;
    float4* __restrict__ o4 = (float4*)out;
    const int stride = gridDim.x * blockDim.x;
    int i = blockIdx.x * blockDim.x + threadIdx.x;

    // Depth-2 circular register pipeline: two LDG.128 in flight per warp.
    float4 b0, b1;
    if (i < n4)           b0 = x4[i];
    if (i + stride < n4)  b1 = x4[i + stride];

    for (; i < n4; i += stride) {
        int ip2 = i + 2 * stride;
        float4 nxt;
        if (ip2 < n4) nxt = x4[ip2];

        unsigned c0 = lookup(b0.x);
        unsigned c1 = lookup(b0.y);
        unsigned c2 = lookup(b0.z);
        unsigned c3 = lookup(b0.w);

        float r0 = (float)c0, r1 = (float)c1, r2 = (float)c2, r3 = (float)c3;
        if ((c0 | c1 | c2 | c3) & 0x80u) {
            if (c0 & 0x80u) r0 = resolve(c0, b0.x);
            if (c1 & 0x80u) r1 = resolve(c1, b0.y);
            if (c2 & 0x80u) r2 = resolve(c2, b0.z);
            if (c3 & 0x80u) r3 = resolve(c3, b0.w);
        }
        __stcs(&o4[i], make_float4(r0, r1, r2, r3));
        b0 = b1;
        b1 = nxt;
    }

    for (int t = (n4 << 2) + blockIdx.x * blockDim.x + threadIdx.x; t < n; t += stride)
        out[t] = vq_full_fallback(x[t], scoef);
}

extern "C" void kernel_launch(void* const* d_in, const int* in_sizes, int n_in,
                              void* d_out, int out_size)
{
    const float* x   = (const float*)d_in[0];
    const float* emb = (const float*)d_in[1];
    if (n_in >= 2 && in_sizes[0] == KC * DC && in_sizes[1] != KC * DC) {
        x   = (const float*)d_in[1];
        emb = (const float*)d_in[0];
    }
    float* out = (float*)d_out;
    int n = out_size;

    vq_build_lut<<<NBINS / 128, 128>>>(emb);

    // PDL launch; plain-launch fallback if the attribute path errors.
    cudaLaunchConfig_t cfg = {};
    cfg.gridDim  = dim3(592, 1, 1);     // 4 CTAs/SM, one wave
    cfg.blockDim = dim3(256, 1, 1);
    cfg.dynamicSmemBytes = 0;
    cfg.stream = 0;
    cudaLaunchAttribute attr[1];
    attr[0].id = cudaLaunchAttributeProgrammaticStreamSerialization;
    attr[0].val.programmaticStreamSerializationAllowed = 1;
    cfg.attrs = attr;
    cfg.numAttrs = 1;
    cudaError_t err = cudaLaunchKernelEx(&cfg, vq_map, x, emb, out, n);
    if (err != cudaSuccess) {
        (void)cudaGetLastError();
        vq_map<<<592, 256>>>(x, emb, out, n);
    }
}